// round 12
// baseline (speedup 1.0000x reference)
#include <cuda_runtime.h>
#include <cstdint>

#define BATCH 16
#define NPROP 2048
#define NCLS 80
#define NCLS1 81
#define KTOP 2048
#define CAP 16384
#define SCORE_THR 0.05f
#define IOU_THR 0.5f
#define MAXR 4.135166556742356f
#define OUTK 100
#define HISTN 3072
#define BINS 2304
#define SLOTS 4096
#define NT 1024
#define BPI 64          // blocks per image (64 * 32 proposals = 2048)

typedef unsigned long long ull;
typedef unsigned char uchar;

// ---------------- device scratch ----------------
__device__ ull g_keys[BATCH][CAP];
__device__ int g_cnt[BATCH];     // zero-init; reset by worker
__device__ int g_done[BATCH];    // zero-init; reset by worker
__device__ ull g_skey[BATCH][KTOP];

__device__ __forceinline__ int score_bin(unsigned u) {
    int bn = (int)(u >> 14) - 62770;
    return min(max(bn, 0), BINS - 1);
}

// ---------------- single fused kernel ----------------
// dynamic smem union (72 KB):
//  phase A (softmax):  ull  sbuf[640]                       @0
//  phase B (select):   ull  tmpk[4096] @0 | hist @32768 | base @45056  (57344)
//  phase C (nms/emit): f4 sobox[2048] @0 | f4 sbout[2048] @32768 |
//                      slab @65536 | salive @67584 | clist(short) @69632 (73728)
#define SMEM_DYN 73728
extern __shared__ char dyn[];

__global__ void __launch_bounds__(NT, 2) k_all(const float* __restrict__ cls,
                                               const float* __restrict__ reg,
                                               const float* __restrict__ props,
                                               const int* __restrict__ hw,
                                               float* __restrict__ out) {
    int b = blockIdx.x >> 6;
    int tid = threadIdx.x;
    int lane = tid & 31;
    int warp = tid >> 5;

    __shared__ int s_cnt, s_gbase, s_last, s_total;
    __shared__ int s_wsum[32];
    __shared__ int c_cnt[NCLS], c_base2[NCLS];

    // ================= phase A: softmax + compaction (one proposal per warp) ===
    ull* sbuf = (ull*)dyn;
    if (tid == 0) s_cnt = 0;
    __syncthreads();

    int gw = blockIdx.x * 32 + warp;          // global proposal id
    int n = gw & (NPROP - 1);
    const float* x = cls + (size_t)gw * NCLS1;
    float v0 = x[lane];
    float v1 = x[lane + 32];
    float v2 = (lane < 17) ? x[lane + 64] : -3.4e38f;
    float m = fmaxf(fmaxf(v0, v1), v2);
#pragma unroll
    for (int o = 16; o > 0; o >>= 1) m = fmaxf(m, __shfl_xor_sync(0xffffffffu, m, o));
    float e0 = expf(v0 - m);
    float e1 = expf(v1 - m);
    float e2 = (lane < 17) ? expf(v2 - m) : 0.0f;
    float s = e0 + e1 + e2;
#pragma unroll
    for (int o = 16; o > 0; o >>= 1) s += __shfl_xor_sync(0xffffffffu, s, o);

    auto push = [&](bool cond, float p, unsigned idx) {
        unsigned mask = __ballot_sync(0xffffffffu, cond);
        if (cond) {
            unsigned u = __float_as_uint(p);
            int leader = __ffs(mask) - 1;
            int base0 = 0;
            if (lane == leader) base0 = atomicAdd(&s_cnt, __popc(mask));
            base0 = __shfl_sync(mask, base0, leader);
            sbuf[base0 + __popc(mask & ((1u << lane) - 1))] = ((ull)(~u) << 32) | idx;
        }
    };
    float p0 = e0 / s;
    push(p0 > SCORE_THR, p0, (unsigned)(n * NCLS + lane));
    float p1 = e1 / s;
    push(p1 > SCORE_THR, p1, (unsigned)(n * NCLS + lane + 32));
    float p2 = e2 / s;
    push((lane < 16) && (p2 > SCORE_THR), p2, (unsigned)(n * NCLS + lane + 64));
    __syncthreads();

    if (tid == 0) s_gbase = atomicAdd(&g_cnt[b], s_cnt);
    __syncthreads();
    int bcnt = s_cnt, gbase = s_gbase;
    for (int i = tid; i < bcnt; i += NT)
        if (gbase + i < CAP) g_keys[b][gbase + i] = sbuf[i];

    // ================= arrival: last block becomes worker =====================
    __threadfence();
    if (tid == 0) {
        int old = atomicAdd(&g_done[b], 1);
        s_last = (old == BPI - 1);
    }
    __syncthreads();
    if (!s_last) return;
    __threadfence();   // acquire other blocks' g_keys writes
    if (tid == 0) {
        g_done[b] = 0;
        s_cnt = g_cnt[b];    // reuse s_cnt as image candidate count
        g_cnt[b] = 0;
    }
    __syncthreads();
    int cnt = min(s_cnt, CAP);

    // ================= phase B: hist + suffix scan + scatter + rank ===========
    ull* tmpk = (ull*)dyn;
    int* hist = (int*)(dyn + 32768);
    int* base = (int*)(dyn + 45056);

    for (int i = tid; i < HISTN; i += NT) hist[i] = 0;
    __syncthreads();
    for (int i = tid; i < cnt; i += NT)
        atomicAdd(&hist[score_bin(~(unsigned)(g_keys[b][i] >> 32))], 1);
    __syncthreads();

    int h0 = hist[3 * tid], h1 = hist[3 * tid + 1], h2 = hist[3 * tid + 2];
    int loc = h0 + h1 + h2;
    int v = loc;
#pragma unroll
    for (int o = 1; o < 32; o <<= 1) {
        int u = __shfl_down_sync(0xffffffffu, v, o);
        if (lane + o < 32) v += u;
    }
    if (lane == 0) s_wsum[warp] = v;
    __syncthreads();
    if (warp == 0) {
        int wv = s_wsum[lane];
#pragma unroll
        for (int o = 1; o < 32; o <<= 1) {
            int u = __shfl_down_sync(0xffffffffu, wv, o);
            if (lane + o < 32) wv += u;
        }
        s_wsum[lane] = wv;
    }
    __syncthreads();
    int beyondW = (warp < 31) ? s_wsum[warp + 1] : 0;
    int beyond = v + beyondW - loc;
    base[3 * tid + 2] = beyond;
    base[3 * tid + 1] = beyond + h2;
    base[3 * tid] = beyond + h2 + h1;
    int S_total = s_wsum[0];
    __syncthreads();

    for (int i = tid; i < HISTN; i += NT) hist[i] = 0;
    __syncthreads();
    for (int i = tid; i < cnt; i += NT) {
        ull k = g_keys[b][i];
        int bb = score_bin(~(unsigned)(k >> 32));
        int st = base[bb];
        if (st >= SLOTS) continue;
        int pos = st + atomicAdd(&hist[bb], 1);
        if (pos < SLOTS) tmpk[pos] = k;
    }
    __syncthreads();

    int validcnt = min(S_total, KTOP);

    // exact-rank placement -> g_skey (global; read back after barrier)
    int S_use = min(S_total, SLOTS);
    for (int i = tid; i < S_use; i += NT) {
        ull key = tmpk[i];
        int bb = score_bin(~(unsigned)(key >> 32));
        int st = base[bb];
        if (st >= KTOP) continue;
        int en = min(st + hist[bb], SLOTS);
        int r = 0;
        for (int j = st; j < en; j++) r += (tmpk[j] < key);
        int pos = st + r;
        if (pos < KTOP) g_skey[b][pos] = key;
    }
    __syncthreads();   // tmpk/hist/base dead; smem reused below

    // ================= phase C: decode + per-class NMS + emit =================
    float4* sobox = (float4*)dyn;
    float4* sbout = (float4*)(dyn + 32768);
    uchar* slab = (uchar*)(dyn + 65536);
    uchar* salive = (uchar*)(dyn + 67584);
    short* clist = (short*)(dyn + 69632);

    float h = (float)hw[b * 2];
    float w = (float)hw[b * 2 + 1];
    float offmul = fmaxf(w, h) + 1.0f;

    for (int i = tid; i < KTOP; i += NT) {
        if (i >= validcnt) { slab[i] = 255; salive[i] = 0; continue; }
        ull key = g_skey[b][i];
        unsigned idx = (unsigned)key;
        int np = (int)(idx / NCLS);
        int c = (int)(idx % NCLS);
        const float* pr = props + ((size_t)b * NPROP + np) * 4;
        float q0 = pr[0], q1 = pr[1], q2 = pr[2], q3 = pr[3];
        float px = (q0 + q2) * 0.5f;
        float py = (q1 + q3) * 0.5f;
        float pw = q2 - q0;
        float ph = q3 - q1;
        const float* dd = reg + ((size_t)b * NPROP + np) * (NCLS * 4) + c * 4;
        float dx = dd[0] * 0.1f;
        float dy = dd[1] * 0.1f;
        float dw = fminf(fmaxf(dd[2] * 0.2f, -MAXR), MAXR);
        float dh = fminf(fmaxf(dd[3] * 0.2f, -MAXR), MAXR);
        float gwd = pw * expf(dw);
        float ghd = ph * expf(dh);
        float gx = px + pw * dx;
        float gy = py + ph * dy;
        float x1 = fminf(fmaxf(gx - 0.5f * gwd, 0.f), w);
        float y1 = fminf(fmaxf(gy - 0.5f * ghd, 0.f), h);
        float x2 = fminf(fmaxf(gx + 0.5f * gwd, 0.f), w);
        float y2 = fminf(fmaxf(gy + 0.5f * ghd, 0.f), h);
        float off = (float)c * offmul;
        sbout[i] = make_float4(x1, y1, x2, y2);
        sobox[i] = make_float4(x1 + off, y1 + off, x2 + off, y2 + off);
        slab[i] = (uchar)c;
        salive[i] = 1;
    }
    if (tid < NCLS) c_cnt[tid] = 0;
    __syncthreads();
    for (int i = tid; i < validcnt; i += NT)
        atomicAdd(&c_cnt[(int)slab[i]], 1);
    __syncthreads();

    // exclusive prefix over 80 class counts (warp 0)
    if (warp == 0) {
        int a = (lane < NCLS) ? c_cnt[lane] : 0;
        int b2 = (lane + 32 < NCLS) ? c_cnt[lane + 32] : 0;
        int c3 = (lane + 64 < NCLS) ? c_cnt[lane + 64] : 0;
        int sa = a, sb2 = b2, sc3 = c3;
#pragma unroll
        for (int o = 1; o < 32; o <<= 1) {
            int u = __shfl_up_sync(0xffffffffu, sa, o); if (lane >= o) sa += u;
            int u2 = __shfl_up_sync(0xffffffffu, sb2, o); if (lane >= o) sb2 += u2;
            int u3 = __shfl_up_sync(0xffffffffu, sc3, o); if (lane >= o) sc3 += u3;
        }
        int totA = __shfl_sync(0xffffffffu, sa, 31);
        int totB = __shfl_sync(0xffffffffu, sb2, 31);
        if (lane < NCLS) c_base2[lane] = sa - a;
        if (lane + 32 < NCLS) c_base2[lane + 32] = totA + sb2 - b2;
        if (lane + 64 < NCLS) c_base2[lane + 64] = totA + totB + sc3 - c3;
    }
    __syncthreads();

    // per-class NMS: warp handles classes {warp, warp+32, warp+64}
    for (int c = warp; c < NCLS; c += 32) {
        int cb = c_base2[c];
        int wr = 0;
        for (int k0 = 0; k0 < validcnt; k0 += 32) {
            int i = k0 + lane;
            bool mine = (i < validcnt) && ((int)slab[i] == c);
            unsigned mm = __ballot_sync(0xffffffffu, mine);
            if (mine) clist[cb + wr + __popc(mm & ((1u << lane) - 1))] = (short)i;
            wr += __popc(mm);
        }
        __syncwarp(0xffffffffu);
        int n2 = wr;
        for (int s2 = 0; s2 < n2; s2++) {
            int is = clist[cb + s2];
            if (!salive[is]) continue;
            float4 A = sobox[is];
            float areaA = fmaxf(A.z - A.x, 0.f) * fmaxf(A.w - A.y, 0.f);
            for (int t = s2 + 1 + lane; t < n2; t += 32) {
                int jt = clist[cb + t];
                if (!salive[jt]) continue;
                float4 q = sobox[jt];
                float inter = fmaxf(fminf(A.z, q.z) - fmaxf(A.x, q.x), 0.f) *
                              fmaxf(fminf(A.w, q.w) - fmaxf(A.y, q.y), 0.f);
                float areaB = fmaxf(q.z - q.x, 0.f) * fmaxf(q.w - q.y, 0.f);
                float uni = areaA + areaB - inter;
                if (uni > 0.f && inter > IOU_THR * uni) salive[jt] = 0;
            }
            __syncwarp(0xffffffffu);
        }
    }
    __syncthreads();

    // emit: prefix over keep flags, first 100 in sorted order
    int i0 = 2 * tid, i1 = 2 * tid + 1;
    int a0 = salive[i0], a1 = salive[i1];
    int ps = a0 + a1;
    int sc = ps;
#pragma unroll
    for (int o = 1; o < 32; o <<= 1) {
        int u = __shfl_up_sync(0xffffffffu, sc, o);
        if (lane >= o) sc += u;
    }
    if (lane == 31) s_wsum[warp] = sc;
    __syncthreads();
    if (warp == 0) {
        int wv = s_wsum[lane];
#pragma unroll
        for (int o = 1; o < 32; o <<= 1) {
            int u = __shfl_up_sync(0xffffffffu, wv, o);
            if (lane >= o) wv += u;
        }
        s_wsum[lane] = wv;
        if (lane == 31) s_total = wv;
    }
    __syncthreads();
    int wbase = warp ? s_wsum[warp - 1] : 0;
    int excl = wbase + sc - ps;

    if (a0 && excl < OUTK) {
        ull key = g_skey[b][i0];
        ((float4*)out)[b * OUTK + excl] = sbout[i0];
        out[BATCH * OUTK * 4 + b * OUTK + excl] = __uint_as_float(~(unsigned)(key >> 32));
        out[BATCH * OUTK * 5 + b * OUTK + excl] = (float)((unsigned)key % NCLS);
    }
    int r1 = excl + a0;
    if (a1 && r1 < OUTK) {
        ull key = g_skey[b][i1];
        ((float4*)out)[b * OUTK + r1] = sbout[i1];
        out[BATCH * OUTK * 4 + b * OUTK + r1] = __uint_as_float(~(unsigned)(key >> 32));
        out[BATCH * OUTK * 5 + b * OUTK + r1] = (float)((unsigned)key % NCLS);
    }
    int kept = min(s_total, OUTK);
    for (int r = kept + tid; r < OUTK; r += NT) {
        ((float4*)out)[b * OUTK + r] = make_float4(0.f, 0.f, 0.f, 0.f);
        out[BATCH * OUTK * 4 + b * OUTK + r] = 0.0f;
        out[BATCH * OUTK * 5 + b * OUTK + r] = -1.0f;
    }
}

// ---------------- launch ----------------
extern "C" void kernel_launch(void* const* d_in, const int* in_sizes, int n_in,
                              void* d_out, int out_size) {
    const float* cls = (const float*)d_in[0];   // [16,2048,81]
    const float* reg = (const float*)d_in[1];   // [16,2048,320]
    const float* props = (const float*)d_in[2]; // [16,2048,4]
    const int* hw = (const int*)d_in[3];        // [16,2]
    float* out = (float*)d_out;

    cudaFuncSetAttribute(k_all,
                         cudaFuncAttributeMaxDynamicSharedMemorySize, SMEM_DYN);

    k_all<<<BATCH * BPI, NT, SMEM_DYN>>>(cls, reg, props, hw, out);
}

// round 14
// speedup vs baseline: 2.1392x; 2.1392x over previous
#include <cuda_runtime.h>
#include <cstdint>

#define BATCH 16
#define NPROP 2048
#define NCLS 80
#define NCLS1 81
#define KTOP 2048
#define CAP 16384
#define SCORE_THR 0.05f
#define IOU_THR 0.5f
#define MAXR 4.135166556742356f
#define OUTK 100
#define HISTN 3072
#define BINS 2304
#define SLOTS 4096
#define NT 1024

typedef unsigned long long ull;
typedef unsigned char uchar;

// ---------------- device scratch ----------------
__device__ ull g_keys[BATCH][CAP];
__device__ int g_cnt[BATCH];            // zero-init; reset in k_select
__device__ ull g_skey[BATCH][KTOP];
__device__ int g_valid[BATCH];
__device__ float4 g_obox[BATCH][KTOP];  // offset boxes (NMS space)
__device__ float4 g_bout[BATCH][KTOP];  // clipped boxes (output space)
__device__ uchar g_lab[BATCH][KTOP];
__device__ uchar g_alive[BATCH][KTOP];
__device__ int g_done[BATCH];           // zero-init; reset by emitter block

__device__ __forceinline__ int score_bin(unsigned u) {
    int bn = (int)(u >> 14) - 62770;
    return min(max(bn, 0), BINS - 1);
}

// ---------------- 1: softmax + threshold + block-aggregated compaction ----------------
__global__ void k_softmax_compact(const float* __restrict__ cls) {
    __shared__ int s_cnt, s_base;
    __shared__ ull s_buf[176];
    int tid = threadIdx.x;
    int lane = tid & 31;
    int w = tid >> 5;
    int gw = blockIdx.x * 8 + w;
    int b = gw >> 11;
    int n = gw & (NPROP - 1);

    if (tid == 0) s_cnt = 0;
    __syncthreads();

    const float* x = cls + (size_t)gw * NCLS1;
    float v0 = x[lane];
    float v1 = x[lane + 32];
    float v2 = (lane < 17) ? x[lane + 64] : -3.4e38f;
    float m = fmaxf(fmaxf(v0, v1), v2);
#pragma unroll
    for (int o = 16; o > 0; o >>= 1) m = fmaxf(m, __shfl_xor_sync(0xffffffffu, m, o));
    float e0 = expf(v0 - m);
    float e1 = expf(v1 - m);
    float e2 = (lane < 17) ? expf(v2 - m) : 0.0f;
    float s = e0 + e1 + e2;
#pragma unroll
    for (int o = 16; o > 0; o >>= 1) s += __shfl_xor_sync(0xffffffffu, s, o);

    auto push = [&](bool cond, float p, unsigned idx) {
        unsigned mask = __ballot_sync(0xffffffffu, cond);
        if (cond) {
            unsigned u = __float_as_uint(p);
            int leader = __ffs(mask) - 1;
            int base = 0;
            if (lane == leader) base = atomicAdd(&s_cnt, __popc(mask));
            base = __shfl_sync(mask, base, leader);
            s_buf[base + __popc(mask & ((1u << lane) - 1))] = ((ull)(~u) << 32) | idx;
        }
    };
    float p0 = e0 / s;
    push(p0 > SCORE_THR, p0, (unsigned)(n * NCLS + lane));
    float p1 = e1 / s;
    push(p1 > SCORE_THR, p1, (unsigned)(n * NCLS + lane + 32));
    float p2 = e2 / s;
    push((lane < 16) && (p2 > SCORE_THR), p2, (unsigned)(n * NCLS + lane + 64));
    __syncthreads();

    if (tid == 0) s_base = atomicAdd(&g_cnt[b], s_cnt);
    __syncthreads();
    int cnt = s_cnt, base = s_base;
    for (int i = tid; i < cnt; i += 256)
        if (base + i < CAP) g_keys[b][base + i] = s_buf[i];
}

// ---------------- 2: select (hist+scan+scatter) + fused rank-place/decode ----------------
// smem: tmpk 32768 | hist 12288 | base 12288 = 57344
#define SMEM_SEL 57344
extern __shared__ char dynsel[];

__global__ void __launch_bounds__(NT) k_select(const float* __restrict__ reg,
                                               const float* __restrict__ props,
                                               const int* __restrict__ hw) {
    int b = blockIdx.x;
    int tid = threadIdx.x;
    int lane = tid & 31;
    int warp = tid >> 5;

    ull* tmpk = (ull*)dynsel;
    int* hist = (int*)(dynsel + 32768);
    int* base = (int*)(dynsel + 45056);
    __shared__ int s_wsum[32];

    int cnt = min(g_cnt[b], CAP);

    for (int i = tid; i < HISTN; i += NT) hist[i] = 0;
    __syncthreads();
    for (int i = tid; i < cnt; i += NT)
        atomicAdd(&hist[score_bin(~(unsigned)(g_keys[b][i] >> 32))], 1);
    __syncthreads();

    int h0 = hist[3 * tid], h1 = hist[3 * tid + 1], h2 = hist[3 * tid + 2];
    int loc = h0 + h1 + h2;
    int v = loc;
#pragma unroll
    for (int o = 1; o < 32; o <<= 1) {
        int u = __shfl_down_sync(0xffffffffu, v, o);
        if (lane + o < 32) v += u;
    }
    if (lane == 0) s_wsum[warp] = v;
    __syncthreads();
    if (warp == 0) {
        int wv = s_wsum[lane];
#pragma unroll
        for (int o = 1; o < 32; o <<= 1) {
            int u = __shfl_down_sync(0xffffffffu, wv, o);
            if (lane + o < 32) wv += u;
        }
        s_wsum[lane] = wv;
    }
    __syncthreads();
    int beyondW = (warp < 31) ? s_wsum[warp + 1] : 0;
    int beyond = v + beyondW - loc;
    base[3 * tid + 2] = beyond;
    base[3 * tid + 1] = beyond + h2;
    base[3 * tid] = beyond + h2 + h1;
    int S_total = s_wsum[0];
    __syncthreads();

    for (int i = tid; i < HISTN; i += NT) hist[i] = 0;
    __syncthreads();
    for (int i = tid; i < cnt; i += NT) {
        ull k = g_keys[b][i];
        int bb = score_bin(~(unsigned)(k >> 32));
        int st = base[bb];
        if (st >= SLOTS) continue;
        int pos = st + atomicAdd(&hist[bb], 1);
        if (pos < SLOTS) tmpk[pos] = k;
    }
    __syncthreads();

    int validcnt = min(S_total, KTOP);
    if (tid == 0) { g_valid[b] = validcnt; g_cnt[b] = 0; }

    float h = (float)hw[b * 2];
    float w = (float)hw[b * 2 + 1];
    float offmul = fmaxf(w, h) + 1.0f;

    int S_use = min(S_total, SLOTS);
    for (int i = tid; i < S_use; i += NT) {
        ull key = tmpk[i];
        int bb = score_bin(~(unsigned)(key >> 32));
        int st = base[bb];
        if (st >= KTOP) continue;
        int en = min(st + hist[bb], SLOTS);
        int r = 0;
        for (int j = st; j < en; j++) r += (tmpk[j] < key);
        int pos = st + r;
        if (pos >= KTOP) continue;

        unsigned idx = (unsigned)key;
        int n = (int)(idx / NCLS);
        int c = (int)(idx % NCLS);
        const float* pr = props + ((size_t)b * NPROP + n) * 4;
        float p0 = pr[0], p1 = pr[1], p2 = pr[2], p3 = pr[3];
        float px = (p0 + p2) * 0.5f;
        float py = (p1 + p3) * 0.5f;
        float pw = p2 - p0;
        float ph = p3 - p1;
        const float* dd = reg + ((size_t)b * NPROP + n) * (NCLS * 4) + c * 4;
        float dx = dd[0] * 0.1f;
        float dy = dd[1] * 0.1f;
        float dw = fminf(fmaxf(dd[2] * 0.2f, -MAXR), MAXR);
        float dh = fminf(fmaxf(dd[3] * 0.2f, -MAXR), MAXR);
        float gw = pw * expf(dw);
        float gh = ph * expf(dh);
        float gx = px + pw * dx;
        float gy = py + ph * dy;
        float x1 = fminf(fmaxf(gx - 0.5f * gw, 0.f), w);
        float y1 = fminf(fmaxf(gy - 0.5f * gh, 0.f), h);
        float x2 = fminf(fmaxf(gx + 0.5f * gw, 0.f), w);
        float y2 = fminf(fmaxf(gy + 0.5f * gh, 0.f), h);
        float off = (float)c * offmul;
        g_skey[b][pos] = key;
        g_bout[b][pos] = make_float4(x1, y1, x2, y2);
        g_obox[b][pos] = make_float4(x1 + off, y1 + off, x2 + off, y2 + off);
        g_lab[b][pos] = (uchar)c;
        g_alive[b][pos] = 1;
    }
    for (int i = validcnt + tid; i < KTOP; i += NT) {
        g_lab[b][i] = 255;
        g_alive[b][i] = 0;
    }
}

// ---------------- 3: gather-NMS (register alive, dense members) + emit ----------------
// grid = BATCH*10, 256 threads (8 warps); warp handles class cg*8+warp
// smem: sbox float4[2048] @0 | clist short[2048] @32768 | slab @36864 = 38912
#define SMEM_NMS 38912
extern __shared__ char dynnms[];

__global__ void __launch_bounds__(256) k_nms_out(float* __restrict__ out) {
    int b = blockIdx.x / 10;
    int cg = blockIdx.x % 10;
    int tid = threadIdx.x;
    int lane = tid & 31;
    int warp = tid >> 5;

    float4* sbox = (float4*)dynnms;
    short* clist = (short*)(dynnms + 32768);
    uchar* slab = (uchar*)(dynnms + 36864);
    __shared__ int s_cnt8[8], s_base8[8];
    __shared__ int s_last, s_total;
    __shared__ int s_wsum[8];

    int valid = g_valid[b];

    for (int i = tid; i < KTOP; i += 256) slab[i] = g_lab[b][i];
    __syncthreads();

    int c = cg * 8 + warp;
    // pass 1: count members (ordered ballot scan)
    int n2 = 0;
    for (int k0 = 0; k0 < valid; k0 += 32) {
        bool mine = (k0 + lane < valid) && ((int)slab[k0 + lane] == c);
        n2 += __popc(__ballot_sync(0xffffffffu, mine));
    }
    if (lane == 0) s_cnt8[warp] = n2;
    __syncthreads();
    if (tid == 0) {
        int acc = 0;
        for (int k = 0; k < 8; k++) { s_base8[k] = acc; acc += s_cnt8[k]; }
    }
    __syncthreads();
    int cb = s_base8[warp];

    // pass 2: fill ordered member list + gather member boxes into dense smem
    int wr = 0;
    for (int k0 = 0; k0 < valid; k0 += 32) {
        bool mine = (k0 + lane < valid) && ((int)slab[k0 + lane] == c);
        unsigned mm = __ballot_sync(0xffffffffu, mine);
        if (mine) clist[cb + wr + __popc(mm & ((1u << lane) - 1))] = (short)(k0 + lane);
        wr += __popc(mm);
    }
    __syncwarp(0xffffffffu);
    for (int t = lane; t < n2; t += 32)
        sbox[cb + t] = g_obox[b][clist[cb + t]];
    __syncwarp(0xffffffffu);

    // greedy NMS: register alive mask (lane owns member t = lane + 32k)
    ull alive = 0;
    {
        int mycnt = (n2 > lane) ? ((n2 - 1 - lane) / 32 + 1) : 0;
        alive = (mycnt >= 64) ? ~0ULL : ((1ULL << mycnt) - 1ULL);
    }
    for (int s2 = 0; s2 < n2; s2++) {
        ull w = __shfl_sync(0xffffffffu, alive, s2 & 31);
        if (!((w >> (s2 >> 5)) & 1ULL)) continue;   // uniform: all lanes share w
        float4 A = sbox[cb + s2];
        float areaA = fmaxf(A.z - A.x, 0.f) * fmaxf(A.w - A.y, 0.f);
        ull m = alive;
        while (m) {
            int k = __ffsll((long long)m) - 1;
            m &= m - 1;
            int t = lane + (k << 5);
            if (t > s2) {
                float4 q = sbox[cb + t];
                float inter = fmaxf(fminf(A.z, q.z) - fmaxf(A.x, q.x), 0.f) *
                              fmaxf(fminf(A.w, q.w) - fmaxf(A.y, q.y), 0.f);
                float areaB = fmaxf(q.z - q.x, 0.f) * fmaxf(q.w - q.y, 0.f);
                float uni = areaA + areaB - inter;
                if (uni > 0.f && inter > IOU_THR * uni) {
                    alive &= ~(1ULL << k);
                    g_alive[b][clist[cb + t]] = 0;
                }
            }
        }
    }
    __syncthreads();

    // ---- last block per image emits ----
    if (tid == 0) {
        __threadfence();
        int old = atomicAdd(&g_done[b], 1);
        s_last = (old == 9);
    }
    __syncthreads();
    if (!s_last) return;
    __threadfence();
    if (tid == 0) g_done[b] = 0;

    int a[8], ps = 0;
#pragma unroll
    for (int k = 0; k < 8; k++) { a[k] = g_alive[b][8 * tid + k]; ps += a[k]; }
    int sc = ps;
#pragma unroll
    for (int o = 1; o < 32; o <<= 1) {
        int u = __shfl_up_sync(0xffffffffu, sc, o);
        if (lane >= o) sc += u;
    }
    if (lane == 31) s_wsum[warp] = sc;
    __syncthreads();
    if (warp == 0 && lane < 8) {
        int wv = s_wsum[lane];
#pragma unroll
        for (int o = 1; o < 8; o <<= 1) {
            int u = __shfl_up_sync(0x000000ffu, wv, o);
            if (lane >= o) wv += u;
        }
        s_wsum[lane] = wv;
        if (lane == 7) s_total = wv;
    }
    __syncthreads();
    int wbase = warp ? s_wsum[warp - 1] : 0;
    int run = wbase + sc - ps;

#pragma unroll
    for (int k = 0; k < 8; k++) {
        if (a[k] && run < OUTK) {
            int i = 8 * tid + k;
            ull key = g_skey[b][i];
            ((float4*)out)[b * OUTK + run] = g_bout[b][i];
            out[BATCH * OUTK * 4 + b * OUTK + run] = __uint_as_float(~(unsigned)(key >> 32));
            out[BATCH * OUTK * 5 + b * OUTK + run] = (float)((unsigned)key % NCLS);
        }
        run += a[k];
    }
    int kept = min(s_total, OUTK);
    for (int r = kept + tid; r < OUTK; r += 256) {
        ((float4*)out)[b * OUTK + r] = make_float4(0.f, 0.f, 0.f, 0.f);
        out[BATCH * OUTK * 4 + b * OUTK + r] = 0.0f;
        out[BATCH * OUTK * 5 + b * OUTK + r] = -1.0f;
    }
}

// ---------------- launch ----------------
extern "C" void kernel_launch(void* const* d_in, const int* in_sizes, int n_in,
                              void* d_out, int out_size) {
    const float* cls = (const float*)d_in[0];   // [16,2048,81]
    const float* reg = (const float*)d_in[1];   // [16,2048,320]
    const float* props = (const float*)d_in[2]; // [16,2048,4]
    const int* hw = (const int*)d_in[3];        // [16,2]
    float* out = (float*)d_out;

    cudaFuncSetAttribute(k_select,
                         cudaFuncAttributeMaxDynamicSharedMemorySize, SMEM_SEL);
    cudaFuncSetAttribute(k_nms_out,
                         cudaFuncAttributeMaxDynamicSharedMemorySize, SMEM_NMS);

    k_softmax_compact<<<BATCH * NPROP / 8, 256>>>(cls);
    k_select<<<BATCH, NT, SMEM_SEL>>>(reg, props, hw);
    k_nms_out<<<BATCH * 10, 256, SMEM_NMS>>>(out);
}

// round 15
// speedup vs baseline: 2.3185x; 1.0838x over previous
#include <cuda_runtime.h>
#include <cstdint>

#define BATCH 16
#define NPROP 2048
#define NCLS 80
#define NCLS1 81
#define KTOP 2048
#define CAP 16384
#define SCORE_THR 0.05f
#define IOU_THR 0.5f
#define MAXR 4.135166556742356f
#define OUTK 100
#define HISTN 3072
#define BINS 2304
#define SLOTS 4096
#define NT 1024

typedef unsigned long long ull;
typedef unsigned char uchar;

// ---------------- device scratch ----------------
__device__ ull g_keys[BATCH][CAP];
__device__ int g_cnt[BATCH];            // zero-init; reset in k_select
__device__ ull g_skey[BATCH][KTOP];
__device__ int g_valid[BATCH];
__device__ float4 g_obox[BATCH][KTOP];  // offset boxes (NMS space)
__device__ float4 g_bout[BATCH][KTOP];  // clipped boxes (output space)
__device__ uchar g_lab[BATCH][KTOP];
__device__ uchar g_alive[BATCH][KTOP];

__device__ __forceinline__ int score_bin(unsigned u) {
    int bn = (int)(u >> 14) - 62770;
    return min(max(bn, 0), BINS - 1);
}

// ---------------- 1: softmax + threshold + block-aggregated compaction ----------------
__global__ void k_softmax_compact(const float* __restrict__ cls) {
    __shared__ int s_cnt, s_base;
    __shared__ ull s_buf[176];
    int tid = threadIdx.x;
    int lane = tid & 31;
    int w = tid >> 5;
    int gw = blockIdx.x * 8 + w;
    int b = gw >> 11;
    int n = gw & (NPROP - 1);

    if (tid == 0) s_cnt = 0;
    __syncthreads();

    const float* x = cls + (size_t)gw * NCLS1;
    float v0 = x[lane];
    float v1 = x[lane + 32];
    float v2 = (lane < 17) ? x[lane + 64] : -3.4e38f;
    float m = fmaxf(fmaxf(v0, v1), v2);
#pragma unroll
    for (int o = 16; o > 0; o >>= 1) m = fmaxf(m, __shfl_xor_sync(0xffffffffu, m, o));
    float e0 = expf(v0 - m);
    float e1 = expf(v1 - m);
    float e2 = (lane < 17) ? expf(v2 - m) : 0.0f;
    float s = e0 + e1 + e2;
#pragma unroll
    for (int o = 16; o > 0; o >>= 1) s += __shfl_xor_sync(0xffffffffu, s, o);

    auto push = [&](bool cond, float p, unsigned idx) {
        unsigned mask = __ballot_sync(0xffffffffu, cond);
        if (cond) {
            unsigned u = __float_as_uint(p);
            int leader = __ffs(mask) - 1;
            int base = 0;
            if (lane == leader) base = atomicAdd(&s_cnt, __popc(mask));
            base = __shfl_sync(mask, base, leader);
            s_buf[base + __popc(mask & ((1u << lane) - 1))] = ((ull)(~u) << 32) | idx;
        }
    };
    float p0 = e0 / s;
    push(p0 > SCORE_THR, p0, (unsigned)(n * NCLS + lane));
    float p1 = e1 / s;
    push(p1 > SCORE_THR, p1, (unsigned)(n * NCLS + lane + 32));
    float p2 = e2 / s;
    push((lane < 16) && (p2 > SCORE_THR), p2, (unsigned)(n * NCLS + lane + 64));
    __syncthreads();

    if (tid == 0) s_base = atomicAdd(&g_cnt[b], s_cnt);
    __syncthreads();
    int cnt = s_cnt, base = s_base;
    for (int i = tid; i < cnt; i += 256)
        if (base + i < CAP) g_keys[b][base + i] = s_buf[i];
}

// ---------------- 2: select (hist+scan+scatter) + fused rank-place/decode ----------------
// smem: tmpk 32768 | hist 12288 | base 12288 | ctr 12288 = 69632
#define SMEM_SEL 69632
extern __shared__ char dynsel[];

__global__ void __launch_bounds__(NT) k_select(const float* __restrict__ reg,
                                               const float* __restrict__ props,
                                               const int* __restrict__ hw) {
    int b = blockIdx.x;
    int tid = threadIdx.x;
    int lane = tid & 31;
    int warp = tid >> 5;

    ull* tmpk = (ull*)dynsel;
    int* hist = (int*)(dynsel + 32768);
    int* base = (int*)(dynsel + 45056);
    int* ctr = (int*)(dynsel + 57344);
    __shared__ int s_wsum[32];

    int cnt = min(g_cnt[b], CAP);

    for (int i = tid; i < HISTN; i += NT) { hist[i] = 0; ctr[i] = 0; }
    __syncthreads();
    for (int i = tid; i < cnt; i += NT)
        atomicAdd(&hist[score_bin(~(unsigned)(g_keys[b][i] >> 32))], 1);
    __syncthreads();

    int h0 = hist[3 * tid], h1 = hist[3 * tid + 1], h2 = hist[3 * tid + 2];
    int loc = h0 + h1 + h2;
    int v = loc;
#pragma unroll
    for (int o = 1; o < 32; o <<= 1) {
        int u = __shfl_down_sync(0xffffffffu, v, o);
        if (lane + o < 32) v += u;
    }
    if (lane == 0) s_wsum[warp] = v;
    __syncthreads();
    if (warp == 0) {
        int wv = s_wsum[lane];
#pragma unroll
        for (int o = 1; o < 32; o <<= 1) {
            int u = __shfl_down_sync(0xffffffffu, wv, o);
            if (lane + o < 32) wv += u;
        }
        s_wsum[lane] = wv;
    }
    __syncthreads();
    int beyondW = (warp < 31) ? s_wsum[warp + 1] : 0;
    int beyond = v + beyondW - loc;
    base[3 * tid + 2] = beyond;
    base[3 * tid + 1] = beyond + h2;
    base[3 * tid] = beyond + h2 + h1;
    int S_total = s_wsum[0];
    __syncthreads();

    for (int i = tid; i < cnt; i += NT) {
        ull k = g_keys[b][i];
        int bb = score_bin(~(unsigned)(k >> 32));
        int st = base[bb];
        if (st >= SLOTS) continue;
        int pos = st + atomicAdd(&ctr[bb], 1);
        if (pos < SLOTS) tmpk[pos] = k;
    }
    __syncthreads();

    int validcnt = min(S_total, KTOP);
    if (tid == 0) { g_valid[b] = validcnt; g_cnt[b] = 0; }

    float h = (float)hw[b * 2];
    float w = (float)hw[b * 2 + 1];
    float offmul = fmaxf(w, h) + 1.0f;

    int S_use = min(S_total, SLOTS);
    for (int i = tid; i < S_use; i += NT) {
        ull key = tmpk[i];
        int bb = score_bin(~(unsigned)(key >> 32));
        int st = base[bb];
        if (st >= KTOP) continue;
        int en = min(st + ctr[bb], SLOTS);
        int r = 0;
        for (int j = st; j < en; j++) r += (tmpk[j] < key);
        int pos = st + r;
        if (pos >= KTOP) continue;

        unsigned idx = (unsigned)key;
        int n = (int)(idx / NCLS);
        int c = (int)(idx % NCLS);
        const float* pr = props + ((size_t)b * NPROP + n) * 4;
        float p0 = pr[0], p1 = pr[1], p2 = pr[2], p3 = pr[3];
        float px = (p0 + p2) * 0.5f;
        float py = (p1 + p3) * 0.5f;
        float pw = p2 - p0;
        float ph = p3 - p1;
        const float* dd = reg + ((size_t)b * NPROP + n) * (NCLS * 4) + c * 4;
        float dx = dd[0] * 0.1f;
        float dy = dd[1] * 0.1f;
        float dw = fminf(fmaxf(dd[2] * 0.2f, -MAXR), MAXR);
        float dh = fminf(fmaxf(dd[3] * 0.2f, -MAXR), MAXR);
        float gw = pw * expf(dw);
        float gh = ph * expf(dh);
        float gx = px + pw * dx;
        float gy = py + ph * dy;
        float x1 = fminf(fmaxf(gx - 0.5f * gw, 0.f), w);
        float y1 = fminf(fmaxf(gy - 0.5f * gh, 0.f), h);
        float x2 = fminf(fmaxf(gx + 0.5f * gw, 0.f), w);
        float y2 = fminf(fmaxf(gy + 0.5f * gh, 0.f), h);
        float off = (float)c * offmul;
        g_skey[b][pos] = key;
        g_bout[b][pos] = make_float4(x1, y1, x2, y2);
        g_obox[b][pos] = make_float4(x1 + off, y1 + off, x2 + off, y2 + off);
        g_lab[b][pos] = (uchar)c;
        g_alive[b][pos] = 1;
    }
    for (int i = validcnt + tid; i < KTOP; i += NT) {
        g_lab[b][i] = 255;
        g_alive[b][i] = 0;
    }
}

// ---------------- 3: per-class NMS (staged, R8 structure; 16 classes/block) ----------------
// grid = BATCH*5 blocks, 512 threads (16 warps); warp handles class cg*16+warp
// smem: sb float4[2048] @0 | clist short[2048] @32768 | slab @36864 | salive @38912 = 40960
#define SMEM_NMS 40960
extern __shared__ char dynnms[];

__global__ void __launch_bounds__(512) k_nms() {
    int b = blockIdx.x / 5;
    int cg = blockIdx.x % 5;
    int tid = threadIdx.x;
    int lane = tid & 31;
    int warp = tid >> 5;

    float4* sb = (float4*)dynnms;
    short* clist = (short*)(dynnms + 32768);
    uchar* slab = (uchar*)(dynnms + 36864);
    uchar* salive = (uchar*)(dynnms + 38912);
    __shared__ int s_cnt16[16], s_base16[16];

    int valid = g_valid[b];

    for (int i = tid; i < KTOP; i += 512) {
        sb[i] = g_obox[b][i];
        slab[i] = g_lab[b][i];
        salive[i] = g_alive[b][i];
    }
    __syncthreads();

    int c = cg * 16 + warp;
    // pass 1: count members (ordered ballot scan)
    int n2 = 0;
    for (int k0 = 0; k0 < valid; k0 += 32) {
        bool mine = (k0 + lane < valid) && ((int)slab[k0 + lane] == c);
        n2 += __popc(__ballot_sync(0xffffffffu, mine));
    }
    if (lane == 0) s_cnt16[warp] = n2;
    __syncthreads();
    if (tid == 0) {
        int acc = 0;
        for (int k = 0; k < 16; k++) { s_base16[k] = acc; acc += s_cnt16[k]; }
    }
    __syncthreads();
    int cb = s_base16[warp];

    // pass 2: fill ordered member list
    int wr = 0;
    for (int k0 = 0; k0 < valid; k0 += 32) {
        bool mine = (k0 + lane < valid) && ((int)slab[k0 + lane] == c);
        unsigned mm = __ballot_sync(0xffffffffu, mine);
        if (mine) clist[cb + wr + __popc(mm & ((1u << lane) - 1))] = (short)(k0 + lane);
        wr += __popc(mm);
    }
    __syncwarp(0xffffffffu);

    // greedy NMS within class (members in score order; area on the fly)
    for (int s2 = 0; s2 < n2; s2++) {
        int is = clist[cb + s2];
        if (!salive[is]) continue;
        float4 A = sb[is];
        float areaA = fmaxf(A.z - A.x, 0.f) * fmaxf(A.w - A.y, 0.f);
        for (int t = s2 + 1 + lane; t < n2; t += 32) {
            int jt = clist[cb + t];
            if (!salive[jt]) continue;
            float4 q = sb[jt];
            float inter = fmaxf(fminf(A.z, q.z) - fmaxf(A.x, q.x), 0.f) *
                          fmaxf(fminf(A.w, q.w) - fmaxf(A.y, q.y), 0.f);
            float areaB = fmaxf(q.z - q.x, 0.f) * fmaxf(q.w - q.y, 0.f);
            float uni = areaA + areaB - inter;
            if (uni > 0.f && inter > IOU_THR * uni) {
                salive[jt] = 0;
                g_alive[b][jt] = 0;
            }
        }
        __syncwarp(0xffffffffu);
    }
}

// ---------------- 4: prefix over keep flags + emit top-100 ----------------
__global__ void __launch_bounds__(NT) k_out(float* __restrict__ out) {
    int b = blockIdx.x;
    int tid = threadIdx.x;
    int lane = tid & 31;
    int warp = tid >> 5;
    __shared__ int s_wsum[32];
    __shared__ int s_total;

    int i0 = 2 * tid, i1 = 2 * tid + 1;
    int a0 = g_alive[b][i0], a1 = g_alive[b][i1];
    int ps = a0 + a1;
    int sc = ps;
#pragma unroll
    for (int o = 1; o < 32; o <<= 1) {
        int u = __shfl_up_sync(0xffffffffu, sc, o);
        if (lane >= o) sc += u;
    }
    if (lane == 31) s_wsum[warp] = sc;
    __syncthreads();
    if (warp == 0) {
        int wv = s_wsum[lane];
#pragma unroll
        for (int o = 1; o < 32; o <<= 1) {
            int u = __shfl_up_sync(0xffffffffu, wv, o);
            if (lane >= o) wv += u;
        }
        s_wsum[lane] = wv;
        if (lane == 31) s_total = wv;
    }
    __syncthreads();
    int wbase = warp ? s_wsum[warp - 1] : 0;
    int excl = wbase + sc - ps;

    if (a0 && excl < OUTK) {
        ull key = g_skey[b][i0];
        ((float4*)out)[b * OUTK + excl] = g_bout[b][i0];
        out[BATCH * OUTK * 4 + b * OUTK + excl] = __uint_as_float(~(unsigned)(key >> 32));
        out[BATCH * OUTK * 5 + b * OUTK + excl] = (float)((unsigned)key % NCLS);
    }
    int r1 = excl + a0;
    if (a1 && r1 < OUTK) {
        ull key = g_skey[b][i1];
        ((float4*)out)[b * OUTK + r1] = g_bout[b][i1];
        out[BATCH * OUTK * 4 + b * OUTK + r1] = __uint_as_float(~(unsigned)(key >> 32));
        out[BATCH * OUTK * 5 + b * OUTK + r1] = (float)((unsigned)key % NCLS);
    }
    int kept = min(s_total, OUTK);
    for (int r = kept + tid; r < OUTK; r += NT) {
        ((float4*)out)[b * OUTK + r] = make_float4(0.f, 0.f, 0.f, 0.f);
        out[BATCH * OUTK * 4 + b * OUTK + r] = 0.0f;
        out[BATCH * OUTK * 5 + b * OUTK + r] = -1.0f;
    }
}

// ---------------- launch ----------------
extern "C" void kernel_launch(void* const* d_in, const int* in_sizes, int n_in,
                              void* d_out, int out_size) {
    const float* cls = (const float*)d_in[0];   // [16,2048,81]
    const float* reg = (const float*)d_in[1];   // [16,2048,320]
    const float* props = (const float*)d_in[2]; // [16,2048,4]
    const int* hw = (const int*)d_in[3];        // [16,2]
    float* out = (float*)d_out;

    cudaFuncSetAttribute(k_select,
                         cudaFuncAttributeMaxDynamicSharedMemorySize, SMEM_SEL);
    cudaFuncSetAttribute(k_nms,
                         cudaFuncAttributeMaxDynamicSharedMemorySize, SMEM_NMS);

    k_softmax_compact<<<BATCH * NPROP / 8, 256>>>(cls);
    k_select<<<BATCH, NT, SMEM_SEL>>>(reg, props, hw);
    k_nms<<<BATCH * 5, 512, SMEM_NMS>>>();
    k_out<<<BATCH, NT>>>(out);
}

// round 17
// speedup vs baseline: 2.3230x; 1.0019x over previous
#include <cuda_runtime.h>
#include <cstdint>

#define BATCH 16
#define NPROP 2048
#define NCLS 80
#define NCLS1 81
#define KTOP 2048
#define CAP 16384
#define SCORE_THR 0.05f
#define IOU_THR 0.5f
#define MAXR 4.135166556742356f
#define OUTK 100
#define HISTN 3072
#define BINS 2304
#define SLOTS 4096
#define NT 1024

typedef unsigned long long ull;
typedef unsigned char uchar;

#define GDC_WAIT() asm volatile("griddepcontrol.wait;" ::: "memory")
#define GDC_LAUNCH() asm volatile("griddepcontrol.launch_dependents;" ::: "memory")

// ---------------- device scratch ----------------
__device__ ull g_keys[BATCH][CAP];
__device__ int g_cnt[BATCH];            // zero-init; reset in k_select
__device__ ull g_skey[BATCH][KTOP];
__device__ int g_valid[BATCH];
__device__ float4 g_obox[BATCH][KTOP];  // offset boxes (NMS space)
__device__ float4 g_bout[BATCH][KTOP];  // clipped boxes (output space)
__device__ uchar g_lab[BATCH][KTOP];
__device__ uchar g_alive[BATCH][KTOP];

__device__ __forceinline__ int score_bin(unsigned u) {
    int bn = (int)(u >> 14) - 62770;
    return min(max(bn, 0), BINS - 1);
}

// ---------------- 1: softmax + threshold + block-aggregated compaction ----------------
__global__ void k_softmax_compact(const float* __restrict__ cls) {
    __shared__ int s_cnt, s_base;
    __shared__ ull s_buf[176];
    int tid = threadIdx.x;
    int lane = tid & 31;
    int w = tid >> 5;
    int gw = blockIdx.x * 8 + w;
    int b = gw >> 11;
    int n = gw & (NPROP - 1);

    if (tid == 0) s_cnt = 0;
    __syncthreads();

    const float* x = cls + (size_t)gw * NCLS1;
    float v0 = x[lane];
    float v1 = x[lane + 32];
    float v2 = (lane < 17) ? x[lane + 64] : -3.4e38f;
    float m = fmaxf(fmaxf(v0, v1), v2);
#pragma unroll
    for (int o = 16; o > 0; o >>= 1) m = fmaxf(m, __shfl_xor_sync(0xffffffffu, m, o));
    float e0 = expf(v0 - m);
    float e1 = expf(v1 - m);
    float e2 = (lane < 17) ? expf(v2 - m) : 0.0f;
    float s = e0 + e1 + e2;
#pragma unroll
    for (int o = 16; o > 0; o >>= 1) s += __shfl_xor_sync(0xffffffffu, s, o);

    auto push = [&](bool cond, float p, unsigned idx) {
        unsigned mask = __ballot_sync(0xffffffffu, cond);
        if (cond) {
            unsigned u = __float_as_uint(p);
            int leader = __ffs(mask) - 1;
            int base = 0;
            if (lane == leader) base = atomicAdd(&s_cnt, __popc(mask));
            base = __shfl_sync(mask, base, leader);
            s_buf[base + __popc(mask & ((1u << lane) - 1))] = ((ull)(~u) << 32) | idx;
        }
    };
    // exact-safe pretest: e <= 0.0498*s  =>  round(e/s) < 0.05, so skipping div
    // cannot change the comparison outcome; emitted p is always the exact e/s.
    float thr = 0.0498f * s;
    float p0 = 0.0f;
    if (e0 > thr) p0 = e0 / s;
    push(p0 > SCORE_THR, p0, (unsigned)(n * NCLS + lane));
    float p1 = 0.0f;
    if (e1 > thr) p1 = e1 / s;
    push(p1 > SCORE_THR, p1, (unsigned)(n * NCLS + lane + 32));
    float p2 = 0.0f;
    if (e2 > thr) p2 = e2 / s;
    push((lane < 16) && (p2 > SCORE_THR), p2, (unsigned)(n * NCLS + lane + 64));
    __syncthreads();

    if (tid == 0) s_base = atomicAdd(&g_cnt[b], s_cnt);
    __syncthreads();
    int cnt = s_cnt, base = s_base;
    for (int i = tid; i < cnt; i += 256)
        if (base + i < CAP) g_keys[b][base + i] = s_buf[i];
}

// ---------------- 2: select (hist+scan+scatter) + fused rank-place/decode ----------------
// smem: tmpk 32768 | hist 12288 | base 12288 | ctr 12288 = 69632
#define SMEM_SEL 69632
extern __shared__ char dynsel[];

__global__ void __launch_bounds__(NT) k_select(const float* __restrict__ reg,
                                               const float* __restrict__ props,
                                               const int* __restrict__ hw) {
    GDC_WAIT();
    GDC_LAUNCH();
    int b = blockIdx.x;
    int tid = threadIdx.x;
    int lane = tid & 31;
    int warp = tid >> 5;

    ull* tmpk = (ull*)dynsel;
    int* hist = (int*)(dynsel + 32768);
    int* base = (int*)(dynsel + 45056);
    int* ctr = (int*)(dynsel + 57344);
    __shared__ int s_wsum[32];

    int cnt = min(g_cnt[b], CAP);

    for (int i = tid; i < HISTN; i += NT) { hist[i] = 0; ctr[i] = 0; }
    __syncthreads();
    for (int i = tid; i < cnt; i += NT)
        atomicAdd(&hist[score_bin(~(unsigned)(g_keys[b][i] >> 32))], 1);
    __syncthreads();

    int h0 = hist[3 * tid], h1 = hist[3 * tid + 1], h2 = hist[3 * tid + 2];
    int loc = h0 + h1 + h2;
    int v = loc;
#pragma unroll
    for (int o = 1; o < 32; o <<= 1) {
        int u = __shfl_down_sync(0xffffffffu, v, o);
        if (lane + o < 32) v += u;
    }
    if (lane == 0) s_wsum[warp] = v;
    __syncthreads();
    if (warp == 0) {
        int wv = s_wsum[lane];
#pragma unroll
        for (int o = 1; o < 32; o <<= 1) {
            int u = __shfl_down_sync(0xffffffffu, wv, o);
            if (lane + o < 32) wv += u;
        }
        s_wsum[lane] = wv;
    }
    __syncthreads();
    int beyondW = (warp < 31) ? s_wsum[warp + 1] : 0;
    int beyond = v + beyondW - loc;
    base[3 * tid + 2] = beyond;
    base[3 * tid + 1] = beyond + h2;
    base[3 * tid] = beyond + h2 + h1;
    int S_total = s_wsum[0];
    __syncthreads();

    for (int i = tid; i < cnt; i += NT) {
        ull k = g_keys[b][i];
        int bb = score_bin(~(unsigned)(k >> 32));
        int st = base[bb];
        if (st >= SLOTS) continue;
        int pos = st + atomicAdd(&ctr[bb], 1);
        if (pos < SLOTS) tmpk[pos] = k;
    }
    __syncthreads();

    int validcnt = min(S_total, KTOP);
    if (tid == 0) { g_valid[b] = validcnt; g_cnt[b] = 0; }

    float h = (float)hw[b * 2];
    float w = (float)hw[b * 2 + 1];
    float offmul = fmaxf(w, h) + 1.0f;

    int S_use = min(S_total, SLOTS);
    for (int i = tid; i < S_use; i += NT) {
        ull key = tmpk[i];
        int bb = score_bin(~(unsigned)(key >> 32));
        int st = base[bb];
        if (st >= KTOP) continue;
        int en = min(st + ctr[bb], SLOTS);
        int r = 0;
        for (int j = st; j < en; j++) r += (tmpk[j] < key);
        int pos = st + r;
        if (pos >= KTOP) continue;

        unsigned idx = (unsigned)key;
        int n = (int)(idx / NCLS);
        int c = (int)(idx % NCLS);
        const float* pr = props + ((size_t)b * NPROP + n) * 4;
        float p0 = pr[0], p1 = pr[1], p2 = pr[2], p3 = pr[3];
        float px = (p0 + p2) * 0.5f;
        float py = (p1 + p3) * 0.5f;
        float pw = p2 - p0;
        float ph = p3 - p1;
        const float* dd = reg + ((size_t)b * NPROP + n) * (NCLS * 4) + c * 4;
        float dx = dd[0] * 0.1f;
        float dy = dd[1] * 0.1f;
        float dw = fminf(fmaxf(dd[2] * 0.2f, -MAXR), MAXR);
        float dh = fminf(fmaxf(dd[3] * 0.2f, -MAXR), MAXR);
        float gw = pw * expf(dw);
        float gh = ph * expf(dh);
        float gx = px + pw * dx;
        float gy = py + ph * dy;
        float x1 = fminf(fmaxf(gx - 0.5f * gw, 0.f), w);
        float y1 = fminf(fmaxf(gy - 0.5f * gh, 0.f), h);
        float x2 = fminf(fmaxf(gx + 0.5f * gw, 0.f), w);
        float y2 = fminf(fmaxf(gy + 0.5f * gh, 0.f), h);
        float off = (float)c * offmul;
        g_skey[b][pos] = key;
        g_bout[b][pos] = make_float4(x1, y1, x2, y2);
        g_obox[b][pos] = make_float4(x1 + off, y1 + off, x2 + off, y2 + off);
        g_lab[b][pos] = (uchar)c;
        g_alive[b][pos] = 1;
    }
    for (int i = validcnt + tid; i < KTOP; i += NT) {
        g_lab[b][i] = 255;
        g_alive[b][i] = 0;
    }
}

// ---------------- 3: per-class NMS (staged; 16 classes/block) ----------------
// grid = BATCH*5 blocks, 512 threads (16 warps); warp handles class cg*16+warp
// smem: sb float4[2048] @0 | clist short[2048] @32768 | slab @36864 | salive @38912 = 40960
#define SMEM_NMS 40960
extern __shared__ char dynnms[];

__global__ void __launch_bounds__(512) k_nms() {
    GDC_WAIT();
    GDC_LAUNCH();
    int b = blockIdx.x / 5;
    int cg = blockIdx.x % 5;
    int tid = threadIdx.x;
    int lane = tid & 31;
    int warp = tid >> 5;

    float4* sb = (float4*)dynnms;
    short* clist = (short*)(dynnms + 32768);
    uchar* slab = (uchar*)(dynnms + 36864);
    uchar* salive = (uchar*)(dynnms + 38912);
    __shared__ int s_cnt16[16], s_base16[16];

    int valid = g_valid[b];

    for (int i = tid; i < KTOP; i += 512) {
        sb[i] = g_obox[b][i];
        slab[i] = g_lab[b][i];
        salive[i] = g_alive[b][i];
    }
    __syncthreads();

    int c = cg * 16 + warp;
    int n2 = 0;
    for (int k0 = 0; k0 < valid; k0 += 32) {
        bool mine = (k0 + lane < valid) && ((int)slab[k0 + lane] == c);
        n2 += __popc(__ballot_sync(0xffffffffu, mine));
    }
    if (lane == 0) s_cnt16[warp] = n2;
    __syncthreads();
    if (tid == 0) {
        int acc = 0;
        for (int k = 0; k < 16; k++) { s_base16[k] = acc; acc += s_cnt16[k]; }
    }
    __syncthreads();
    int cb = s_base16[warp];

    int wr = 0;
    for (int k0 = 0; k0 < valid; k0 += 32) {
        bool mine = (k0 + lane < valid) && ((int)slab[k0 + lane] == c);
        unsigned mm = __ballot_sync(0xffffffffu, mine);
        if (mine) clist[cb + wr + __popc(mm & ((1u << lane) - 1))] = (short)(k0 + lane);
        wr += __popc(mm);
    }
    __syncwarp(0xffffffffu);

    for (int s2 = 0; s2 < n2; s2++) {
        int is = clist[cb + s2];
        if (!salive[is]) continue;
        float4 A = sb[is];
        float areaA = fmaxf(A.z - A.x, 0.f) * fmaxf(A.w - A.y, 0.f);
        for (int t = s2 + 1 + lane; t < n2; t += 32) {
            int jt = clist[cb + t];
            if (!salive[jt]) continue;
            float4 q = sb[jt];
            float inter = fmaxf(fminf(A.z, q.z) - fmaxf(A.x, q.x), 0.f) *
                          fmaxf(fminf(A.w, q.w) - fmaxf(A.y, q.y), 0.f);
            float areaB = fmaxf(q.z - q.x, 0.f) * fmaxf(q.w - q.y, 0.f);
            float uni = areaA + areaB - inter;
            if (uni > 0.f && inter > IOU_THR * uni) {
                salive[jt] = 0;
                g_alive[b][jt] = 0;
            }
        }
        __syncwarp(0xffffffffu);
    }
}

// ---------------- 4: prefix over keep flags + emit top-100 ----------------
__global__ void __launch_bounds__(NT) k_out(float* __restrict__ out) {
    GDC_WAIT();
    int b = blockIdx.x;
    int tid = threadIdx.x;
    int lane = tid & 31;
    int warp = tid >> 5;
    __shared__ int s_wsum[32];
    __shared__ int s_total;

    int i0 = 2 * tid, i1 = 2 * tid + 1;
    int a0 = g_alive[b][i0], a1 = g_alive[b][i1];
    int ps = a0 + a1;
    int sc = ps;
#pragma unroll
    for (int o = 1; o < 32; o <<= 1) {
        int u = __shfl_up_sync(0xffffffffu, sc, o);
        if (lane >= o) sc += u;
    }
    if (lane == 31) s_wsum[warp] = sc;
    __syncthreads();
    if (warp == 0) {
        int wv = s_wsum[lane];
#pragma unroll
        for (int o = 1; o < 32; o <<= 1) {
            int u = __shfl_up_sync(0xffffffffu, wv, o);
            if (lane >= o) wv += u;
        }
        s_wsum[lane] = wv;
        if (lane == 31) s_total = wv;
    }
    __syncthreads();
    int wbase = warp ? s_wsum[warp - 1] : 0;
    int excl = wbase + sc - ps;

    if (a0 && excl < OUTK) {
        ull key = g_skey[b][i0];
        ((float4*)out)[b * OUTK + excl] = g_bout[b][i0];
        out[BATCH * OUTK * 4 + b * OUTK + excl] = __uint_as_float(~(unsigned)(key >> 32));
        out[BATCH * OUTK * 5 + b * OUTK + excl] = (float)((unsigned)key % NCLS);
    }
    int r1 = excl + a0;
    if (a1 && r1 < OUTK) {
        ull key = g_skey[b][i1];
        ((float4*)out)[b * OUTK + r1] = g_bout[b][i1];
        out[BATCH * OUTK * 4 + b * OUTK + r1] = __uint_as_float(~(unsigned)(key >> 32));
        out[BATCH * OUTK * 5 + b * OUTK + r1] = (float)((unsigned)key % NCLS);
    }
    int kept = min(s_total, OUTK);
    for (int r = kept + tid; r < OUTK; r += NT) {
        ((float4*)out)[b * OUTK + r] = make_float4(0.f, 0.f, 0.f, 0.f);
        out[BATCH * OUTK * 4 + b * OUTK + r] = 0.0f;
        out[BATCH * OUTK * 5 + b * OUTK + r] = -1.0f;
    }
}

// ---------------- launch ----------------
extern "C" void kernel_launch(void* const* d_in, const int* in_sizes, int n_in,
                              void* d_out, int out_size) {
    const float* cls = (const float*)d_in[0];   // [16,2048,81]
    const float* reg = (const float*)d_in[1];   // [16,2048,320]
    const float* props = (const float*)d_in[2]; // [16,2048,4]
    const int* hw = (const int*)d_in[3];        // [16,2]
    float* out = (float*)d_out;

    cudaFuncSetAttribute(k_select,
                         cudaFuncAttributeMaxDynamicSharedMemorySize, SMEM_SEL);
    cudaFuncSetAttribute(k_nms,
                         cudaFuncAttributeMaxDynamicSharedMemorySize, SMEM_NMS);

    k_softmax_compact<<<BATCH * NPROP / 8, 256>>>(cls);

    cudaLaunchAttribute at[1];
    at[0].id = cudaLaunchAttributeProgrammaticStreamSerialization;
    at[0].val.programmaticStreamSerializationAllowed = 1;

    {
        cudaLaunchConfig_t cfg = {};
        cfg.gridDim = dim3(BATCH);
        cfg.blockDim = dim3(NT);
        cfg.dynamicSmemBytes = SMEM_SEL;
        cfg.stream = 0;
        cfg.attrs = at;
        cfg.numAttrs = 1;
        cudaLaunchKernelEx(&cfg, k_select, reg, props, hw);
    }
    {
        cudaLaunchConfig_t cfg = {};
        cfg.gridDim = dim3(BATCH * 5);
        cfg.blockDim = dim3(512);
        cfg.dynamicSmemBytes = SMEM_NMS;
        cfg.stream = 0;
        cfg.attrs = at;
        cfg.numAttrs = 1;
        cudaLaunchKernelEx(&cfg, k_nms);
    }
    {
        cudaLaunchConfig_t cfg = {};
        cfg.gridDim = dim3(BATCH);
        cfg.blockDim = dim3(NT);
        cfg.dynamicSmemBytes = 0;
        cfg.stream = 0;
        cfg.attrs = at;
        cfg.numAttrs = 1;
        cudaLaunchKernelEx(&cfg, k_out, out);
    }
}